// round 13
// baseline (speedup 1.0000x reference)
#include <cuda_runtime.h>
#include <cuda_bf16.h>
#include <cuda_fp16.h>
#include <math.h>
#include <stdint.h>

// Problem constants
#define SEQ    4096
#define DMODEL 1024
#define NHEAD  16
#define HDIM   64
#define HALF   32   // HDIM/2

// ---------------- scratch (device globals) ----------------
__device__ float g_v[(size_t)NHEAD * SEQ * HDIM];   // [h][t][d] fp32
__device__ float g_cos[SEQ * HALF];
__device__ float g_sin[SEQ * HALF];

// fp16 split operands for projections
__device__ __half g_xh[(size_t)SEQ * DMODEL];
__device__ __half g_xl[(size_t)SEQ * DMODEL];
__device__ __half g_yh[(size_t)SEQ * DMODEL];      // attention output hi (written fused)
__device__ __half g_yl[(size_t)SEQ * DMODEL];      //                  lo
__device__ __half g_wq[(size_t)3 * DMODEL * DMODEL];  // w_qkv^T [3072][1024] fp16
__device__ __half g_wp[(size_t)DMODEL * DMODEL];      // w_proj^T [1024][1024] fp16

// fp16 operands for attention (RoPE'd; q pre-scaled by 1/8, split-2; k single; v^T single)
__device__ __half g_qfh[(size_t)NHEAD * SEQ * HDIM];   // [h][t][d] hi
__device__ __half g_qfl[(size_t)NHEAD * SEQ * HDIM];   //            lo
__device__ __half g_kf [(size_t)NHEAD * SEQ * HDIM];   // [h][t][d] single
__device__ __half g_vfh[(size_t)NHEAD * HDIM * SEQ];   // [h][d][t] single (V^T)

// ---------------- helpers ----------------
__device__ __forceinline__ uint32_t smem_to_u32(const void* p) {
    uint32_t a;
    asm("{ .reg .u64 t; cvta.to.shared.u64 t, %1; cvt.u32.u64 %0, t; }" : "=r"(a) : "l"(p));
    return a;
}
__device__ __forceinline__ void ldsm4(uint32_t addr, uint32_t r[4]) {
    asm volatile("ldmatrix.sync.aligned.m8n8.x4.shared.b16 {%0,%1,%2,%3}, [%4];"
                 : "=r"(r[0]), "=r"(r[1]), "=r"(r[2]), "=r"(r[3]) : "r"(addr));
}
__device__ __forceinline__ void mma16816h(float c[4], const uint32_t a[4], uint32_t b0, uint32_t b1) {
    asm volatile("mma.sync.aligned.m16n8k16.row.col.f32.f16.f16.f32 "
                 "{%0,%1,%2,%3}, {%4,%5,%6,%7}, {%8,%9}, {%0,%1,%2,%3};"
                 : "+f"(c[0]), "+f"(c[1]), "+f"(c[2]), "+f"(c[3])
                 : "r"(a[0]), "r"(a[1]), "r"(a[2]), "r"(a[3]), "r"(b0), "r"(b1));
}
#define CP16(dst, src) \
    asm volatile("cp.async.ca.shared.global [%0], [%1], 16;" :: "r"(dst), "l"(__cvta_generic_to_global(src)))
#define CP_COMMIT() asm volatile("cp.async.commit_group;")
#define CP_WAIT(N)  asm volatile("cp.async.wait_group %0;" :: "n"(N))

__device__ __forceinline__ uint32_t pack_h(float a, float b) {
    __half2 h = __floats2half2_rn(a, b);
    return *(uint32_t*)&h;
}

// ---------------- RoPE cos/sin table ----------------
__global__ void rope_table_kernel() {
    int idx = blockIdx.x * blockDim.x + threadIdx.x;
    if (idx >= SEQ * HALF) return;
    int d = idx & (HALF - 1);
    int t = idx >> 5;
    double inv = exp(-log(10000.0) * (double)d / (double)HALF);
    float invf = (float)inv;
    float f = (float)t * invf;
    g_cos[idx] = (float)cos((double)f);
    g_sin[idx] = (float)sin((double)f);
}

// ---------------- fp32 -> fp16 hi/lo split ----------------
__global__ void split_half_kernel(const float* __restrict__ src, __half* __restrict__ hi,
                                  __half* __restrict__ lo, int n) {
    int i = blockIdx.x * blockDim.x + threadIdx.x;
    if (i >= n) return;
    float v = src[i];
    __half h = __float2half_rn(v);
    hi[i] = h;
    lo[i] = __float2half_rn(v - __half2float(h));
}

// ---------------- transpose + fp16: W[K][N] -> Wt [N][K] ----------------
__global__ void transpose_half_kernel(const float* __restrict__ W,
                                      __half* __restrict__ T, int K, int N) {
    __shared__ float t[32][33];
    int n0 = blockIdx.x * 32, k0 = blockIdx.y * 32;
    int tx = threadIdx.x, ty = threadIdx.y;
    #pragma unroll
    for (int r = 0; r < 4; r++)
        t[ty + 8 * r][tx] = W[(size_t)(k0 + ty + 8 * r) * N + n0 + tx];
    __syncthreads();
    #pragma unroll
    for (int r = 0; r < 4; r++)
        T[(size_t)(n0 + ty + 8 * r) * K + k0 + tx] = __float2half_rn(t[tx][ty + 8 * r]);
}

// ---------------- V transpose: g_v [h][t][d] -> vfh [h][d][t] (fp16 single) ----------------
__global__ __launch_bounds__(256) void vsplit_kernel() {
    __shared__ float vs[64][65];
    const int h = blockIdx.y, t0 = blockIdx.x * 64;
    const int tid = threadIdx.x;
    const size_t base_ht = ((size_t)h * SEQ + t0) * HDIM;
    #pragma unroll
    for (int i = 0; i < 16; i++) {
        int idx = tid + i * 256;
        int tl = idx >> 6, d = idx & 63;
        vs[tl][d] = g_v[base_ht + (size_t)tl * HDIM + d];
    }
    __syncthreads();
    #pragma unroll
    for (int i = 0; i < 16; i++) {
        int idx = tid + i * 256;
        int d = idx >> 6, tl = idx & 63;
        g_vfh[((size_t)h * HDIM + d) * SEQ + t0 + tl] = __float2half_rn(vs[tl][d]);
    }
}

// ---------------- mma.sync fp16 split-2 GEMM (reg-staged double buffer; round-9 mainloop) ----------------
// C = A @ B; A fp16 hi/lo [M][K]; B fp16 single, transposed [N][K].
// CTA 128x128, BK=32, 8 warps, warp tile 32x64.
// mode 1: fused RoPE epilogue -> q/k fp16 (+split) and v fp32.  mode 0: fp32 C.
#define BKC 32
#define TS 40
#define TILE_ELEMS (128 * TS)
#define TILE_BYTES (TILE_ELEMS * 2)
#define GEMM_SMEM (6 * TILE_BYTES)     // 2 buffers x 3 tiles = 61440 B

__global__ __launch_bounds__(256, 1) void gemm_mma_kernel(
    const __half* __restrict__ Ah, const __half* __restrict__ Al,
    const __half* __restrict__ B,
    float* __restrict__ C, __half* __restrict__ Qh, __half* __restrict__ Ql,
    __half* __restrict__ Kf, float* __restrict__ V, int N, int K, int mode)
{
    extern __shared__ __half sm_g[];
    const int tid = threadIdx.x;
    const int wid = tid >> 5, lid = tid & 31;
    const int brow = blockIdx.y * 128, bcol = blockIdx.x * 128;
    const int wm = wid >> 1, wn = wid & 1;
    const uint32_t smem_base = smem_to_u32(sm_g);

    const __half* srcs[3] = { Ah, Al, B };

    float acc[2][8][4];
    #pragma unroll
    for (int mi = 0; mi < 2; mi++)
        #pragma unroll
        for (int ni = 0; ni < 8; ni++)
            #pragma unroll
            for (int r = 0; r < 4; r++) acc[mi][ni][r] = 0.f;

    const int rowA = lid & 15;
    const int koA  = (lid >> 4) << 3;
    const int rowB = (lid & 7) + ((lid >> 4) << 3);
    const int koB  = ((lid >> 3) & 1) << 3;

    float4 pre[6];

    auto load_regs = [&](int c) {
        #pragma unroll
        for (int t = 0; t < 3; t++) {
            const __half* s = srcs[t];
            const int rb = (t < 2) ? brow : bcol;
            #pragma unroll
            for (int j = 0; j < 2; j++) {
                int idx = tid + j * 256;
                int row = idx >> 2, g = idx & 3;
                pre[t * 2 + j] = *(const float4*)(s + (size_t)(rb + row) * K + c * BKC + g * 8);
            }
        }
    };
    auto store_smem = [&](int b) {
        #pragma unroll
        for (int t = 0; t < 3; t++) {
            __half* d = sm_g + (b * 3 + t) * TILE_ELEMS;
            #pragma unroll
            for (int j = 0; j < 2; j++) {
                int idx = tid + j * 256;
                int row = idx >> 2, g = idx & 3;
                *(float4*)(d + row * TS + g * 8) = pre[t * 2 + j];
            }
        }
    };
    auto compute = [&](int b) {
        const uint32_t bA_h = smem_base + (uint32_t)(b * 3 + 0) * TILE_BYTES;
        const uint32_t bA_l = smem_base + (uint32_t)(b * 3 + 1) * TILE_BYTES;
        const uint32_t bB   = smem_base + (uint32_t)(b * 3 + 2) * TILE_BYTES;
        #pragma unroll
        for (int ks = 0; ks < 2; ks++) {
            uint32_t ah[2][4], al[2][4];
            #pragma unroll
            for (int mi = 0; mi < 2; mi++) {
                uint32_t off = ((uint32_t)(wm * 32 + mi * 16 + rowA) * TS + ks * 16 + koA) * 2;
                ldsm4(bA_h + off, ah[mi]);
                ldsm4(bA_l + off, al[mi]);
            }
            #pragma unroll
            for (int ni2 = 0; ni2 < 4; ni2++) {
                uint32_t off = ((uint32_t)(wn * 64 + ni2 * 16 + rowB) * TS + ks * 16 + koB) * 2;
                uint32_t bh[4];
                ldsm4(bB + off, bh);
                #pragma unroll
                for (int half2i = 0; half2i < 2; half2i++) {
                    const int ni = ni2 * 2 + half2i;
                    const uint32_t b0 = bh[half2i * 2], b1 = bh[half2i * 2 + 1];
                    #pragma unroll
                    for (int mi = 0; mi < 2; mi++) {
                        mma16816h(acc[mi][ni], ah[mi], b0, b1);
                        mma16816h(acc[mi][ni], al[mi], b0, b1);
                    }
                }
            }
        }
    };

    const int nc = K / BKC;
    load_regs(0);
    store_smem(0);
    for (int c = 0; c < nc; c++) {
        __syncthreads();
        if (c + 1 < nc) load_regs(c + 1);
        compute(c & 1);
        if (c + 1 < nc) store_smem((c + 1) & 1);
    }

    const int gr = lid >> 2, c2v = (lid & 3) * 2;
    if (mode == 1) {
        // fused RoPE + fp16 split epilogue (warp tile = one head).
        #pragma unroll
        for (int mi = 0; mi < 2; mi++) {
            int row0 = brow + wm * 32 + mi * 16 + gr;
            int row1 = row0 + 8;
            #pragma unroll
            for (int ni = 0; ni < 4; ni++) {
                int col = bcol + wn * 64 + ni * 8 + c2v;
                int sect = col >> 10;
                int nn = col & 1023;
                int h = nn >> 6, d = nn & 63;      // d < 32
                float* a0 = acc[mi][ni];
                float* a1 = acc[mi][ni + 4];
                size_t b0 = ((size_t)h * SEQ + row0) * HDIM;
                size_t b1 = ((size_t)h * SEQ + row1) * HDIM;
                if (sect == 2) {
                    *(float2*)&V[b0 + d]      = make_float2(a0[0], a0[1]);
                    *(float2*)&V[b1 + d]      = make_float2(a0[2], a0[3]);
                    *(float2*)&V[b0 + d + 32] = make_float2(a1[0], a1[1]);
                    *(float2*)&V[b1 + d + 32] = make_float2(a1[2], a1[3]);
                } else {
                    float2 c0 = *(const float2*)&g_cos[row0 * HALF + d];
                    float2 s0 = *(const float2*)&g_sin[row0 * HALF + d];
                    float2 c1 = *(const float2*)&g_cos[row1 * HALF + d];
                    float2 s1 = *(const float2*)&g_sin[row1 * HALF + d];
                    float e1[4], e2[4];
                    e1[0] = a0[0] * c0.x - a1[0] * s0.x;  e2[0] = a1[0] * c0.x + a0[0] * s0.x;
                    e1[1] = a0[1] * c0.y - a1[1] * s0.y;  e2[1] = a1[1] * c0.y + a0[1] * s0.y;
                    e1[2] = a0[2] * c1.x - a1[2] * s1.x;  e2[2] = a1[2] * c1.x + a0[2] * s1.x;
                    e1[3] = a0[3] * c1.y - a1[3] * s1.y;  e2[3] = a1[3] * c1.y + a0[3] * s1.y;
                    if (sect == 0) {
                        #pragma unroll
                        for (int r = 0; r < 4; r++) { e1[r] *= 0.125f; e2[r] *= 0.125f; }
                        __half2 h10 = __floats2half2_rn(e1[0], e1[1]);
                        __half2 h12 = __floats2half2_rn(e1[2], e1[3]);
                        __half2 h20 = __floats2half2_rn(e2[0], e2[1]);
                        __half2 h22 = __floats2half2_rn(e2[2], e2[3]);
                        *(__half2*)&Qh[b0 + d]      = h10;
                        *(__half2*)&Qh[b1 + d]      = h12;
                        *(__half2*)&Qh[b0 + d + 32] = h20;
                        *(__half2*)&Qh[b1 + d + 32] = h22;
                        *(__half2*)&Ql[b0 + d] =
                            __floats2half2_rn(e1[0] - __low2float(h10), e1[1] - __high2float(h10));
                        *(__half2*)&Ql[b1 + d] =
                            __floats2half2_rn(e1[2] - __low2float(h12), e1[3] - __high2float(h12));
                        *(__half2*)&Ql[b0 + d + 32] =
                            __floats2half2_rn(e2[0] - __low2float(h20), e2[1] - __high2float(h20));
                        *(__half2*)&Ql[b1 + d + 32] =
                            __floats2half2_rn(e2[2] - __low2float(h22), e2[3] - __high2float(h22));
                    } else {
                        *(__half2*)&Kf[b0 + d]      = __floats2half2_rn(e1[0], e1[1]);
                        *(__half2*)&Kf[b1 + d]      = __floats2half2_rn(e1[2], e1[3]);
                        *(__half2*)&Kf[b0 + d + 32] = __floats2half2_rn(e2[0], e2[1]);
                        *(__half2*)&Kf[b1 + d + 32] = __floats2half2_rn(e2[2], e2[3]);
                    }
                }
            }
        }
    } else {
        #pragma unroll
        for (int mi = 0; mi < 2; mi++) {
            #pragma unroll
            for (int ni = 0; ni < 8; ni++) {
                int row0 = brow + wm * 32 + mi * 16 + gr;
                int col  = bcol + wn * 64 + ni * 8 + c2v;
                *(float2*)&C[(size_t)row0 * N + col] =
                    make_float2(acc[mi][ni][0], acc[mi][ni][1]);
                *(float2*)&C[(size_t)(row0 + 8) * N + col] =
                    make_float2(acc[mi][ni][2], acc[mi][ni][3]);
            }
        }
    }
}

// ---------------- Flash attention via mma.sync (Q split-2, K/P/V single, causal) ----------------
#define PADK 72
#define PADV 136
#define KT_B (128 * PADK * 2)           // 18432 B
#define VT_B (64 * PADV * 2)            // 17408 B
#define BUF_B (KT_B + VT_B)             // 35840 B
// Steady state uses 2*BUF_B = 71680; Q-tile staging transiently needs BUF_B + 2*KT_B.
#define ATTN_SMEM (BUF_B + 2 * KT_B)    // 72704 B

__global__ __launch_bounds__(256, 1) void attn_mma_kernel(
    const __half* __restrict__ Qfh, const __half* __restrict__ Qfl,
    const __half* __restrict__ Kf,
    const __half* __restrict__ Vfh,
    __half* __restrict__ Yh, __half* __restrict__ Yl)
{
    extern __shared__ char asmem[];
    const uint32_t sb = smem_to_u32(asmem);
    const int tid = threadIdx.x;
    const int wid = tid >> 5, lid = tid & 31;
    const int h = blockIdx.y;
    const int qt = gridDim.x - 1 - blockIdx.x;      // longest-first
    const int q0 = qt * 128;

    const __half* pQh = Qfh + (size_t)h * SEQ * HDIM;
    const __half* pQl = Qfl + (size_t)h * SEQ * HDIM;
    const __half* pK  = Kf  + (size_t)h * SEQ * HDIM;
    const __half* pVh = Vfh + (size_t)h * HDIM * SEQ;

    #pragma unroll
    for (int i = 0; i < 4; i++) {
        int idx = tid + i * 256;
        int row = idx >> 3, g = idx & 7;
        *(float4*)(asmem + BUF_B + row * (PADK * 2) + g * 16) =
            *(const float4*)(pQh + (size_t)(q0 + row) * HDIM + g * 8);
        *(float4*)(asmem + BUF_B + KT_B + row * (PADK * 2) + g * 16) =
            *(const float4*)(pQl + (size_t)(q0 + row) * HDIM + g * 8);
    }
    __syncthreads();

    const int rowA = lid & 15;
    const int koA  = (lid >> 4) << 3;
    const int rowB = (lid & 7) + ((lid >> 4) << 3);
    const int koB  = ((lid >> 3) & 1) << 3;

    uint32_t qfh[4][4], qfl[4][4];
    #pragma unroll
    for (int ks = 0; ks < 4; ks++) {
        uint32_t off = ((uint32_t)(wid * 16 + rowA) * PADK + ks * 16 + koA) * 2;
        ldsm4(sb + BUF_B + off, qfh[ks]);
        ldsm4(sb + BUF_B + KT_B + off, qfl[ks]);
    }
    __syncthreads();

    float S[16][4], O[8][4];
    float m0 = -1e30f, m1 = -1e30f, l0 = 0.f, l1 = 0.f;
    #pragma unroll
    for (int i = 0; i < 8; i++)
        #pragma unroll
        for (int r = 0; r < 4; r++) O[i][r] = 0.f;

    auto issue = [&](int j) {
        uint32_t b = sb + (uint32_t)(j & 1) * BUF_B;
        int k0 = j * 128;
        #pragma unroll
        for (int i = 0; i < 4; i++) {
            int idx = tid + i * 256;
            int row = idx >> 3, g = idx & 7;
            CP16(b + (uint32_t)(row * (PADK * 2) + g * 16),
                 pK + (size_t)(k0 + row) * HDIM + g * 8);
        }
        #pragma unroll
        for (int i = 0; i < 4; i++) {
            int idx = tid + i * 256;
            int row = idx >> 4, g = idx & 15;
            CP16(b + KT_B + (uint32_t)(row * (PADV * 2) + g * 16),
                 pVh + (size_t)row * SEQ + k0 + g * 8);
        }
        CP_COMMIT();
    };

    const int gr = lid >> 2, c2 = (lid & 3) * 2;
    const int row0 = q0 + wid * 16 + gr;
    const int row1 = row0 + 8;

    issue(0);
    for (int j = 0; j <= qt; j++) {
        if (j < qt) { issue(j + 1); CP_WAIT(1); }
        else        { CP_WAIT(0); }
        __syncthreads();
        const uint32_t b = sb + (uint32_t)(j & 1) * BUF_B;

        #pragma unroll
        for (int ni = 0; ni < 16; ni++)
            #pragma unroll
            for (int r = 0; r < 4; r++) S[ni][r] = 0.f;

        #pragma unroll
        for (int nt = 0; nt < 8; nt++) {
            #pragma unroll
            for (int ks = 0; ks < 4; ks++) {
                uint32_t off = ((uint32_t)(nt * 16 + rowB) * PADK + ks * 16 + koB) * 2;
                uint32_t bh[4];
                ldsm4(b + off, bh);
                mma16816h(S[2 * nt],     qfh[ks], bh[0], bh[1]);
                mma16816h(S[2 * nt],     qfl[ks], bh[0], bh[1]);
                mma16816h(S[2 * nt + 1], qfh[ks], bh[2], bh[3]);
                mma16816h(S[2 * nt + 1], qfl[ks], bh[2], bh[3]);
            }
        }

        if (j == qt) {
            #pragma unroll
            for (int ni = 0; ni < 16; ni++) {
                int kc = j * 128 + ni * 8 + c2;
                if (kc     > row0) S[ni][0] = -1e30f;
                if (kc + 1 > row0) S[ni][1] = -1e30f;
                if (kc     > row1) S[ni][2] = -1e30f;
                if (kc + 1 > row1) S[ni][3] = -1e30f;
            }
        }

        float mx0 = -1e30f, mx1 = -1e30f;
        #pragma unroll
        for (int ni = 0; ni < 16; ni++) {
            mx0 = fmaxf(mx0, fmaxf(S[ni][0], S[ni][1]));
            mx1 = fmaxf(mx1, fmaxf(S[ni][2], S[ni][3]));
        }
        mx0 = fmaxf(mx0, __shfl_xor_sync(0xffffffffu, mx0, 1));
        mx0 = fmaxf(mx0, __shfl_xor_sync(0xffffffffu, mx0, 2));
        mx1 = fmaxf(mx1, __shfl_xor_sync(0xffffffffu, mx1, 1));
        mx1 = fmaxf(mx1, __shfl_xor_sync(0xffffffffu, mx1, 2));
        float mn0 = fmaxf(m0, mx0), mn1 = fmaxf(m1, mx1);
        float corr0 = __expf(m0 - mn0), corr1 = __expf(m1 - mn1);
        m0 = mn0; m1 = mn1;

        float rs0 = 0.f, rs1 = 0.f;
        #pragma unroll
        for (int ni = 0; ni < 16; ni++) {
            float p0 = __expf(S[ni][0] - mn0);
            float p1 = __expf(S[ni][1] - mn0);
            float p2 = __expf(S[ni][2] - mn1);
            float p3 = __expf(S[ni][3] - mn1);
            S[ni][0] = p0; S[ni][1] = p1; S[ni][2] = p2; S[ni][3] = p3;
            rs0 += p0 + p1;
            rs1 += p2 + p3;
        }
        rs0 += __shfl_xor_sync(0xffffffffu, rs0, 1);
        rs0 += __shfl_xor_sync(0xffffffffu, rs0, 2);
        rs1 += __shfl_xor_sync(0xffffffffu, rs1, 1);
        rs1 += __shfl_xor_sync(0xffffffffu, rs1, 2);
        l0 = l0 * corr0 + rs0;
        l1 = l1 * corr1 + rs1;
        #pragma unroll
        for (int nd = 0; nd < 8; nd++) {
            O[nd][0] *= corr0; O[nd][1] *= corr0;
            O[nd][2] *= corr1; O[nd][3] *= corr1;
        }

        #pragma unroll
        for (int kt = 0; kt < 8; kt++) {
            uint32_t a[4];
            a[0] = pack_h(S[2 * kt][0],     S[2 * kt][1]);
            a[1] = pack_h(S[2 * kt][2],     S[2 * kt][3]);
            a[2] = pack_h(S[2 * kt + 1][0], S[2 * kt + 1][1]);
            a[3] = pack_h(S[2 * kt + 1][2], S[2 * kt + 1][3]);
            #pragma unroll
            for (int nd = 0; nd < 4; nd++) {
                uint32_t off = ((uint32_t)(nd * 16 + rowB) * PADV + kt * 16 + koB) * 2;
                uint32_t vh[4];
                ldsm4(b + KT_B + off, vh);
                mma16816h(O[2 * nd],     a, vh[0], vh[1]);
                mma16816h(O[2 * nd + 1], a, vh[2], vh[3]);
            }
        }
        __syncthreads();
    }

    // ---- epilogue: fused fp16 hi/lo split write ----
    float inv0 = 1.f / l0, inv1 = 1.f / l1;
    #pragma unroll
    for (int nd = 0; nd < 8; nd++) {
        int d = h * HDIM + nd * 8 + c2;
        float o00 = O[nd][0] * inv0, o01 = O[nd][1] * inv0;
        float o10 = O[nd][2] * inv1, o11 = O[nd][3] * inv1;
        __half2 h0 = __floats2half2_rn(o00, o01);
        __half2 h1 = __floats2half2_rn(o10, o11);
        *(__half2*)&Yh[(size_t)row0 * DMODEL + d] = h0;
        *(__half2*)&Yh[(size_t)row1 * DMODEL + d] = h1;
        *(__half2*)&Yl[(size_t)row0 * DMODEL + d] =
            __floats2half2_rn(o00 - __low2float(h0), o01 - __high2float(h0));
        *(__half2*)&Yl[(size_t)row1 * DMODEL + d] =
            __floats2half2_rn(o10 - __low2float(h1), o11 - __high2float(h1));
    }
}

// ---------------- launch ----------------
extern "C" void kernel_launch(void* const* d_in, const int* in_sizes, int n_in,
                              void* d_out, int out_size) {
    const float* x      = (const float*)d_in[0];
    const float* w_qkv  = (const float*)d_in[1];
    const float* w_proj = (const float*)d_in[2];
    float* out = (float*)d_out;
    (void)in_sizes; (void)n_in; (void)out_size;

    float *p_v;
    __half *p_xh, *p_xl, *p_yh, *p_yl, *p_wq, *p_wp;
    __half *p_qfh, *p_qfl, *p_kf, *p_vfh;
    cudaGetSymbolAddress((void**)&p_v,  g_v);
    cudaGetSymbolAddress((void**)&p_xh, g_xh);
    cudaGetSymbolAddress((void**)&p_xl, g_xl);
    cudaGetSymbolAddress((void**)&p_yh, g_yh);
    cudaGetSymbolAddress((void**)&p_yl, g_yl);
    cudaGetSymbolAddress((void**)&p_wq, g_wq);
    cudaGetSymbolAddress((void**)&p_wp, g_wp);
    cudaGetSymbolAddress((void**)&p_qfh, g_qfh);
    cudaGetSymbolAddress((void**)&p_qfl, g_qfl);
    cudaGetSymbolAddress((void**)&p_kf,  g_kf);
    cudaGetSymbolAddress((void**)&p_vfh, g_vfh);

    cudaFuncSetAttribute(gemm_mma_kernel, cudaFuncAttributeMaxDynamicSharedMemorySize, GEMM_SMEM);
    cudaFuncSetAttribute(attn_mma_kernel, cudaFuncAttributeMaxDynamicSharedMemorySize, ATTN_SMEM);

    // 1. RoPE tables (needed by QKV epilogue)
    rope_table_kernel<<<(SEQ * HALF + 255) / 256, 256>>>();

    // 2. prep: x split (fp16), w_qkv transpose (fp16 single)
    split_half_kernel<<<(SEQ * DMODEL + 255) / 256, 256>>>(x, p_xh, p_xl, SEQ * DMODEL);
    {
        dim3 grid(3 * DMODEL / 32, DMODEL / 32);
        transpose_half_kernel<<<grid, dim3(32, 8)>>>(w_qkv, p_wq, DMODEL, 3 * DMODEL);
    }

    // 3. QKV projection with fused RoPE epilogue -> qfh/qfl, kf (fp16), v (fp32)
    {
        dim3 grid(3 * DMODEL / 128, SEQ / 128);
        gemm_mma_kernel<<<grid, 256, GEMM_SMEM>>>(p_xh, p_xl, p_wq,
                                                  nullptr, p_qfh, p_qfl, p_kf, p_v,
                                                  3 * DMODEL, DMODEL, 1);
    }

    // 4. V transpose (fp16 single)
    {
        dim3 grid(SEQ / 64, NHEAD);
        vsplit_kernel<<<grid, 256>>>();
    }

    // 5. flash attention on tensor cores; writes yh/yl fp16 split directly
    {
        dim3 grid(SEQ / 128, NHEAD);
        attn_mma_kernel<<<grid, 256, ATTN_SMEM>>>(p_qfh, p_qfl, p_kf, p_vfh, p_yh, p_yl);
    }

    // 6. output projection (w_proj transpose prepped here; independent of attention)
    {
        dim3 grid(DMODEL / 32, DMODEL / 32);
        transpose_half_kernel<<<grid, dim3(32, 8)>>>(w_proj, p_wp, DMODEL, DMODEL);
    }
    {
        dim3 grid(DMODEL / 128, SEQ / 128);
        gemm_mma_kernel<<<grid, 256, GEMM_SMEM>>>(p_yh, p_yl, p_wp,
                                                  out, nullptr, nullptr, nullptr, nullptr,
                                                  DMODEL, DMODEL, 0);
    }
}

// round 14
// speedup vs baseline: 1.5457x; 1.5457x over previous
#include <cuda_runtime.h>
#include <cuda_bf16.h>
#include <cuda_fp16.h>
#include <math.h>
#include <stdint.h>

// Problem constants
#define SEQ    4096
#define DMODEL 1024
#define NHEAD  16
#define HDIM   64
#define HALF   32   // HDIM/2

// ---------------- scratch (device globals) ----------------
__device__ float g_v[(size_t)NHEAD * SEQ * HDIM];   // [h][t][d] fp32
__device__ float g_cos[SEQ * HALF];
__device__ float g_sin[SEQ * HALF];

// fp16 split operands for projections
__device__ __half g_xh[(size_t)SEQ * DMODEL];
__device__ __half g_xl[(size_t)SEQ * DMODEL];
__device__ __half g_yh[(size_t)SEQ * DMODEL];      // attention output hi (written fused)
__device__ __half g_yl[(size_t)SEQ * DMODEL];      //                  lo
__device__ __half g_wq[(size_t)3 * DMODEL * DMODEL];  // w_qkv^T [3072][1024] fp16
__device__ __half g_wp[(size_t)DMODEL * DMODEL];      // w_proj^T [1024][1024] fp16

// fp16 operands for attention (RoPE'd; q pre-scaled by 1/8, split-2; k single; v^T single)
__device__ __half g_qfh[(size_t)NHEAD * SEQ * HDIM];   // [h][t][d] hi
__device__ __half g_qfl[(size_t)NHEAD * SEQ * HDIM];   //            lo
__device__ __half g_kf [(size_t)NHEAD * SEQ * HDIM];   // [h][t][d] single
__device__ __half g_vfh[(size_t)NHEAD * HDIM * SEQ];   // [h][d][t] single (V^T)

// ---------------- helpers ----------------
__device__ __forceinline__ uint32_t smem_to_u32(const void* p) {
    uint32_t a;
    asm("{ .reg .u64 t; cvta.to.shared.u64 t, %1; cvt.u32.u64 %0, t; }" : "=r"(a) : "l"(p));
    return a;
}
__device__ __forceinline__ void ldsm4(uint32_t addr, uint32_t r[4]) {
    asm volatile("ldmatrix.sync.aligned.m8n8.x4.shared.b16 {%0,%1,%2,%3}, [%4];"
                 : "=r"(r[0]), "=r"(r[1]), "=r"(r[2]), "=r"(r[3]) : "r"(addr));
}
__device__ __forceinline__ void mma16816h(float c[4], const uint32_t a[4], uint32_t b0, uint32_t b1) {
    asm volatile("mma.sync.aligned.m16n8k16.row.col.f32.f16.f16.f32 "
                 "{%0,%1,%2,%3}, {%4,%5,%6,%7}, {%8,%9}, {%0,%1,%2,%3};"
                 : "+f"(c[0]), "+f"(c[1]), "+f"(c[2]), "+f"(c[3])
                 : "r"(a[0]), "r"(a[1]), "r"(a[2]), "r"(a[3]), "r"(b0), "r"(b1));
}
#define CP16(dst, src) \
    asm volatile("cp.async.ca.shared.global [%0], [%1], 16;" :: "r"(dst), "l"(__cvta_generic_to_global(src)))
#define CP_COMMIT() asm volatile("cp.async.commit_group;")
#define CP_WAIT(N)  asm volatile("cp.async.wait_group %0;" :: "n"(N))

__device__ __forceinline__ uint32_t pack_h(float a, float b) {
    __half2 h = __floats2half2_rn(a, b);
    return *(uint32_t*)&h;
}

// ---------------- RoPE cos/sin table ----------------
__global__ void rope_table_kernel() {
    int idx = blockIdx.x * blockDim.x + threadIdx.x;
    if (idx >= SEQ * HALF) return;
    int d = idx & (HALF - 1);
    int t = idx >> 5;
    double inv = exp(-log(10000.0) * (double)d / (double)HALF);
    float invf = (float)inv;
    float f = (float)t * invf;
    g_cos[idx] = (float)cos((double)f);
    g_sin[idx] = (float)sin((double)f);
}

// ---------------- fp32 -> fp16 hi/lo split ----------------
__global__ void split_half_kernel(const float* __restrict__ src, __half* __restrict__ hi,
                                  __half* __restrict__ lo, int n) {
    int i = blockIdx.x * blockDim.x + threadIdx.x;
    if (i >= n) return;
    float v = src[i];
    __half h = __float2half_rn(v);
    hi[i] = h;
    lo[i] = __float2half_rn(v - __half2float(h));
}

// ---------------- transpose + fp16: W[K][N] -> Wt [N][K] ----------------
__global__ void transpose_half_kernel(const float* __restrict__ W,
                                      __half* __restrict__ T, int K, int N) {
    __shared__ float t[32][33];
    int n0 = blockIdx.x * 32, k0 = blockIdx.y * 32;
    int tx = threadIdx.x, ty = threadIdx.y;
    #pragma unroll
    for (int r = 0; r < 4; r++)
        t[ty + 8 * r][tx] = W[(size_t)(k0 + ty + 8 * r) * N + n0 + tx];
    __syncthreads();
    #pragma unroll
    for (int r = 0; r < 4; r++)
        T[(size_t)(n0 + ty + 8 * r) * K + k0 + tx] = __float2half_rn(t[tx][ty + 8 * r]);
}

// ---------------- V transpose: g_v [h][t][d] -> vfh [h][d][t] (fp16 single) ----------------
__global__ __launch_bounds__(256) void vsplit_kernel() {
    __shared__ float vs[64][65];
    const int h = blockIdx.y, t0 = blockIdx.x * 64;
    const int tid = threadIdx.x;
    const size_t base_ht = ((size_t)h * SEQ + t0) * HDIM;
    #pragma unroll
    for (int i = 0; i < 16; i++) {
        int idx = tid + i * 256;
        int tl = idx >> 6, d = idx & 63;
        vs[tl][d] = g_v[base_ht + (size_t)tl * HDIM + d];
    }
    __syncthreads();
    #pragma unroll
    for (int i = 0; i < 16; i++) {
        int idx = tid + i * 256;
        int d = idx >> 6, tl = idx & 63;
        g_vfh[((size_t)h * HDIM + d) * SEQ + t0 + tl] = __float2half_rn(vs[tl][d]);
    }
}

// ---------------- mma.sync fp16 split-2 GEMM (reg-staged double buffer) ----------------
// C = A @ B; A fp16 hi/lo [M][K]; B fp16 single, transposed [N][K].
// CTA 128x128, BK=32, 8 warps, warp tile 32x64.
// mode 1: fused RoPE epilogue -> q/k fp16 (+split) and v fp32.  mode 0: fp32 C.
#define BKC 32
#define TS 40
#define TILE_ELEMS (128 * TS)
#define TILE_BYTES (TILE_ELEMS * 2)
#define GEMM_SMEM (6 * TILE_BYTES)     // 2 buffers x 3 tiles = 61440 B

__global__ __launch_bounds__(256, 1) void gemm_mma_kernel(
    const __half* __restrict__ Ah, const __half* __restrict__ Al,
    const __half* __restrict__ B,
    float* __restrict__ C, __half* __restrict__ Qh, __half* __restrict__ Ql,
    __half* __restrict__ Kf, float* __restrict__ V, int N, int K, int mode)
{
    extern __shared__ __half sm_g[];
    const int tid = threadIdx.x;
    const int wid = tid >> 5, lid = tid & 31;
    const int brow = blockIdx.y * 128, bcol = blockIdx.x * 128;
    const int wm = wid >> 1, wn = wid & 1;
    const uint32_t smem_base = smem_to_u32(sm_g);

    const __half* srcs[3] = { Ah, Al, B };

    float acc[2][8][4];
    #pragma unroll
    for (int mi = 0; mi < 2; mi++)
        #pragma unroll
        for (int ni = 0; ni < 8; ni++)
            #pragma unroll
            for (int r = 0; r < 4; r++) acc[mi][ni][r] = 0.f;

    const int rowA = lid & 15;
    const int koA  = (lid >> 4) << 3;
    const int rowB = (lid & 7) + ((lid >> 4) << 3);
    const int koB  = ((lid >> 3) & 1) << 3;

    float4 pre[6];

    auto load_regs = [&](int c) {
        #pragma unroll
        for (int t = 0; t < 3; t++) {
            const __half* s = srcs[t];
            const int rb = (t < 2) ? brow : bcol;
            #pragma unroll
            for (int j = 0; j < 2; j++) {
                int idx = tid + j * 256;
                int row = idx >> 2, g = idx & 3;
                pre[t * 2 + j] = *(const float4*)(s + (size_t)(rb + row) * K + c * BKC + g * 8);
            }
        }
    };
    auto store_smem = [&](int b) {
        #pragma unroll
        for (int t = 0; t < 3; t++) {
            __half* d = sm_g + (b * 3 + t) * TILE_ELEMS;
            #pragma unroll
            for (int j = 0; j < 2; j++) {
                int idx = tid + j * 256;
                int row = idx >> 2, g = idx & 3;
                *(float4*)(d + row * TS + g * 8) = pre[t * 2 + j];
            }
        }
    };
    auto compute = [&](int b) {
        const uint32_t bA_h = smem_base + (uint32_t)(b * 3 + 0) * TILE_BYTES;
        const uint32_t bA_l = smem_base + (uint32_t)(b * 3 + 1) * TILE_BYTES;
        const uint32_t bB   = smem_base + (uint32_t)(b * 3 + 2) * TILE_BYTES;
        #pragma unroll
        for (int ks = 0; ks < 2; ks++) {
            uint32_t ah[2][4], al[2][4];
            #pragma unroll
            for (int mi = 0; mi < 2; mi++) {
                uint32_t off = ((uint32_t)(wm * 32 + mi * 16 + rowA) * TS + ks * 16 + koA) * 2;
                ldsm4(bA_h + off, ah[mi]);
                ldsm4(bA_l + off, al[mi]);
            }
            #pragma unroll
            for (int ni2 = 0; ni2 < 4; ni2++) {
                uint32_t off = ((uint32_t)(wn * 64 + ni2 * 16 + rowB) * TS + ks * 16 + koB) * 2;
                uint32_t bh[4];
                ldsm4(bB + off, bh);
                #pragma unroll
                for (int half2i = 0; half2i < 2; half2i++) {
                    const int ni = ni2 * 2 + half2i;
                    const uint32_t b0 = bh[half2i * 2], b1 = bh[half2i * 2 + 1];
                    #pragma unroll
                    for (int mi = 0; mi < 2; mi++) {
                        mma16816h(acc[mi][ni], ah[mi], b0, b1);
                        mma16816h(acc[mi][ni], al[mi], b0, b1);
                    }
                }
            }
        }
    };

    const int nc = K / BKC;
    load_regs(0);
    store_smem(0);
    for (int c = 0; c < nc; c++) {
        __syncthreads();
        if (c + 1 < nc) load_regs(c + 1);
        compute(c & 1);
        if (c + 1 < nc) store_smem((c + 1) & 1);
    }

    const int gr = lid >> 2, c2v = (lid & 3) * 2;
    if (mode == 1) {
        // fused RoPE + fp16 split epilogue (warp tile = one head).
        #pragma unroll
        for (int mi = 0; mi < 2; mi++) {
            int row0 = brow + wm * 32 + mi * 16 + gr;
            int row1 = row0 + 8;
            #pragma unroll
            for (int ni = 0; ni < 4; ni++) {
                int col = bcol + wn * 64 + ni * 8 + c2v;
                int sect = col >> 10;
                int nn = col & 1023;
                int h = nn >> 6, d = nn & 63;      // d < 32
                float* a0 = acc[mi][ni];
                float* a1 = acc[mi][ni + 4];
                size_t b0 = ((size_t)h * SEQ + row0) * HDIM;
                size_t b1 = ((size_t)h * SEQ + row1) * HDIM;
                if (sect == 2) {
                    *(float2*)&V[b0 + d]      = make_float2(a0[0], a0[1]);
                    *(float2*)&V[b1 + d]      = make_float2(a0[2], a0[3]);
                    *(float2*)&V[b0 + d + 32] = make_float2(a1[0], a1[1]);
                    *(float2*)&V[b1 + d + 32] = make_float2(a1[2], a1[3]);
                } else {
                    float2 c0 = *(const float2*)&g_cos[row0 * HALF + d];
                    float2 s0 = *(const float2*)&g_sin[row0 * HALF + d];
                    float2 c1 = *(const float2*)&g_cos[row1 * HALF + d];
                    float2 s1 = *(const float2*)&g_sin[row1 * HALF + d];
                    float e1[4], e2[4];
                    e1[0] = a0[0] * c0.x - a1[0] * s0.x;  e2[0] = a1[0] * c0.x + a0[0] * s0.x;
                    e1[1] = a0[1] * c0.y - a1[1] * s0.y;  e2[1] = a1[1] * c0.y + a0[1] * s0.y;
                    e1[2] = a0[2] * c1.x - a1[2] * s1.x;  e2[2] = a1[2] * c1.x + a0[2] * s1.x;
                    e1[3] = a0[3] * c1.y - a1[3] * s1.y;  e2[3] = a1[3] * c1.y + a0[3] * s1.y;
                    if (sect == 0) {
                        #pragma unroll
                        for (int r = 0; r < 4; r++) { e1[r] *= 0.125f; e2[r] *= 0.125f; }
                        __half2 h10 = __floats2half2_rn(e1[0], e1[1]);
                        __half2 h12 = __floats2half2_rn(e1[2], e1[3]);
                        __half2 h20 = __floats2half2_rn(e2[0], e2[1]);
                        __half2 h22 = __floats2half2_rn(e2[2], e2[3]);
                        *(__half2*)&Qh[b0 + d]      = h10;
                        *(__half2*)&Qh[b1 + d]      = h12;
                        *(__half2*)&Qh[b0 + d + 32] = h20;
                        *(__half2*)&Qh[b1 + d + 32] = h22;
                        *(__half2*)&Ql[b0 + d] =
                            __floats2half2_rn(e1[0] - __low2float(h10), e1[1] - __high2float(h10));
                        *(__half2*)&Ql[b1 + d] =
                            __floats2half2_rn(e1[2] - __low2float(h12), e1[3] - __high2float(h12));
                        *(__half2*)&Ql[b0 + d + 32] =
                            __floats2half2_rn(e2[0] - __low2float(h20), e2[1] - __high2float(h20));
                        *(__half2*)&Ql[b1 + d + 32] =
                            __floats2half2_rn(e2[2] - __low2float(h22), e2[3] - __high2float(h22));
                    } else {
                        *(__half2*)&Kf[b0 + d]      = __floats2half2_rn(e1[0], e1[1]);
                        *(__half2*)&Kf[b1 + d]      = __floats2half2_rn(e1[2], e1[3]);
                        *(__half2*)&Kf[b0 + d + 32] = __floats2half2_rn(e2[0], e2[1]);
                        *(__half2*)&Kf[b1 + d + 32] = __floats2half2_rn(e2[2], e2[3]);
                    }
                }
            }
        }
    } else {
        #pragma unroll
        for (int mi = 0; mi < 2; mi++) {
            #pragma unroll
            for (int ni = 0; ni < 8; ni++) {
                int row0 = brow + wm * 32 + mi * 16 + gr;
                int col  = bcol + wn * 64 + ni * 8 + c2v;
                *(float2*)&C[(size_t)row0 * N + col] =
                    make_float2(acc[mi][ni][0], acc[mi][ni][1]);
                *(float2*)&C[(size_t)(row0 + 8) * N + col] =
                    make_float2(acc[mi][ni][2], acc[mi][ni][3]);
            }
        }
    }
}

// ---------------- Flash attention via mma.sync (Q split-2, K/P/V single, causal) ----------------
#define PADK 72
#define PADV 136
#define KT_B (128 * PADK * 2)           // 18432 B
#define VT_B (64 * PADV * 2)            // 17408 B
#define BUF_B (KT_B + VT_B)             // 35840 B
// Steady state uses 2*BUF_B = 71680; Q-tile staging transiently needs BUF_B + 2*KT_B.
#define ATTN_SMEM (BUF_B + 2 * KT_B)    // 72704 B

__global__ __launch_bounds__(256, 1) void attn_mma_kernel(
    const __half* __restrict__ Qfh, const __half* __restrict__ Qfl,
    const __half* __restrict__ Kf,
    const __half* __restrict__ Vfh,
    __half* __restrict__ Yh, __half* __restrict__ Yl)
{
    extern __shared__ char asmem[];
    const uint32_t sb = smem_to_u32(asmem);
    const int tid = threadIdx.x;
    const int wid = tid >> 5, lid = tid & 31;
    const int h = blockIdx.y;
    const int qt = gridDim.x - 1 - blockIdx.x;      // longest-first
    const int q0 = qt * 128;

    const __half* pQh = Qfh + (size_t)h * SEQ * HDIM;
    const __half* pQl = Qfl + (size_t)h * SEQ * HDIM;
    const __half* pK  = Kf  + (size_t)h * SEQ * HDIM;
    const __half* pVh = Vfh + (size_t)h * HDIM * SEQ;

    #pragma unroll
    for (int i = 0; i < 4; i++) {
        int idx = tid + i * 256;
        int row = idx >> 3, g = idx & 7;
        *(float4*)(asmem + BUF_B + row * (PADK * 2) + g * 16) =
            *(const float4*)(pQh + (size_t)(q0 + row) * HDIM + g * 8);
        *(float4*)(asmem + BUF_B + KT_B + row * (PADK * 2) + g * 16) =
            *(const float4*)(pQl + (size_t)(q0 + row) * HDIM + g * 8);
    }
    __syncthreads();

    const int rowA = lid & 15;
    const int koA  = (lid >> 4) << 3;
    const int rowB = (lid & 7) + ((lid >> 4) << 3);
    const int koB  = ((lid >> 3) & 1) << 3;

    uint32_t qfh[4][4], qfl[4][4];
    #pragma unroll
    for (int ks = 0; ks < 4; ks++) {
        uint32_t off = ((uint32_t)(wid * 16 + rowA) * PADK + ks * 16 + koA) * 2;
        ldsm4(sb + BUF_B + off, qfh[ks]);
        ldsm4(sb + BUF_B + KT_B + off, qfl[ks]);
    }
    __syncthreads();

    float S[16][4], O[8][4];
    float m0 = -1e30f, m1 = -1e30f, l0 = 0.f, l1 = 0.f;
    #pragma unroll
    for (int i = 0; i < 8; i++)
        #pragma unroll
        for (int r = 0; r < 4; r++) O[i][r] = 0.f;

    auto issue = [&](int j) {
        uint32_t b = sb + (uint32_t)(j & 1) * BUF_B;
        int k0 = j * 128;
        #pragma unroll
        for (int i = 0; i < 4; i++) {
            int idx = tid + i * 256;
            int row = idx >> 3, g = idx & 7;
            CP16(b + (uint32_t)(row * (PADK * 2) + g * 16),
                 pK + (size_t)(k0 + row) * HDIM + g * 8);
        }
        #pragma unroll
        for (int i = 0; i < 4; i++) {
            int idx = tid + i * 256;
            int row = idx >> 4, g = idx & 15;
            CP16(b + KT_B + (uint32_t)(row * (PADV * 2) + g * 16),
                 pVh + (size_t)row * SEQ + k0 + g * 8);
        }
        CP_COMMIT();
    };

    const int gr = lid >> 2, c2 = (lid & 3) * 2;
    const int row0 = q0 + wid * 16 + gr;
    const int row1 = row0 + 8;

    issue(0);
    for (int j = 0; j <= qt; j++) {
        if (j < qt) { issue(j + 1); CP_WAIT(1); }
        else        { CP_WAIT(0); }
        __syncthreads();
        const uint32_t b = sb + (uint32_t)(j & 1) * BUF_B;

        #pragma unroll
        for (int ni = 0; ni < 16; ni++)
            #pragma unroll
            for (int r = 0; r < 4; r++) S[ni][r] = 0.f;

        #pragma unroll
        for (int nt = 0; nt < 8; nt++) {
            #pragma unroll
            for (int ks = 0; ks < 4; ks++) {
                uint32_t off = ((uint32_t)(nt * 16 + rowB) * PADK + ks * 16 + koB) * 2;
                uint32_t bh[4];
                ldsm4(b + off, bh);
                mma16816h(S[2 * nt],     qfh[ks], bh[0], bh[1]);
                mma16816h(S[2 * nt],     qfl[ks], bh[0], bh[1]);
                mma16816h(S[2 * nt + 1], qfh[ks], bh[2], bh[3]);
                mma16816h(S[2 * nt + 1], qfl[ks], bh[2], bh[3]);
            }
        }

        if (j == qt) {
            #pragma unroll
            for (int ni = 0; ni < 16; ni++) {
                int kc = j * 128 + ni * 8 + c2;
                if (kc     > row0) S[ni][0] = -1e30f;
                if (kc + 1 > row0) S[ni][1] = -1e30f;
                if (kc     > row1) S[ni][2] = -1e30f;
                if (kc + 1 > row1) S[ni][3] = -1e30f;
            }
        }

        float mx0 = -1e30f, mx1 = -1e30f;
        #pragma unroll
        for (int ni = 0; ni < 16; ni++) {
            mx0 = fmaxf(mx0, fmaxf(S[ni][0], S[ni][1]));
            mx1 = fmaxf(mx1, fmaxf(S[ni][2], S[ni][3]));
        }
        mx0 = fmaxf(mx0, __shfl_xor_sync(0xffffffffu, mx0, 1));
        mx0 = fmaxf(mx0, __shfl_xor_sync(0xffffffffu, mx0, 2));
        mx1 = fmaxf(mx1, __shfl_xor_sync(0xffffffffu, mx1, 1));
        mx1 = fmaxf(mx1, __shfl_xor_sync(0xffffffffu, mx1, 2));
        float mn0 = fmaxf(m0, mx0), mn1 = fmaxf(m1, mx1);
        float corr0 = __expf(m0 - mn0), corr1 = __expf(m1 - mn1);
        m0 = mn0; m1 = mn1;

        float rs0 = 0.f, rs1 = 0.f;
        #pragma unroll
        for (int ni = 0; ni < 16; ni++) {
            float p0 = __expf(S[ni][0] - mn0);
            float p1 = __expf(S[ni][1] - mn0);
            float p2 = __expf(S[ni][2] - mn1);
            float p3 = __expf(S[ni][3] - mn1);
            S[ni][0] = p0; S[ni][1] = p1; S[ni][2] = p2; S[ni][3] = p3;
            rs0 += p0 + p1;
            rs1 += p2 + p3;
        }
        rs0 += __shfl_xor_sync(0xffffffffu, rs0, 1);
        rs0 += __shfl_xor_sync(0xffffffffu, rs0, 2);
        rs1 += __shfl_xor_sync(0xffffffffu, rs1, 1);
        rs1 += __shfl_xor_sync(0xffffffffu, rs1, 2);
        l0 = l0 * corr0 + rs0;
        l1 = l1 * corr1 + rs1;
        #pragma unroll
        for (int nd = 0; nd < 8; nd++) {
            O[nd][0] *= corr0; O[nd][1] *= corr0;
            O[nd][2] *= corr1; O[nd][3] *= corr1;
        }

        #pragma unroll
        for (int kt = 0; kt < 8; kt++) {
            uint32_t a[4];
            a[0] = pack_h(S[2 * kt][0],     S[2 * kt][1]);
            a[1] = pack_h(S[2 * kt][2],     S[2 * kt][3]);
            a[2] = pack_h(S[2 * kt + 1][0], S[2 * kt + 1][1]);
            a[3] = pack_h(S[2 * kt + 1][2], S[2 * kt + 1][3]);
            #pragma unroll
            for (int nd = 0; nd < 4; nd++) {
                uint32_t off = ((uint32_t)(nd * 16 + rowB) * PADV + kt * 16 + koB) * 2;
                uint32_t vh[4];
                ldsm4(b + KT_B + off, vh);
                mma16816h(O[2 * nd],     a, vh[0], vh[1]);
                mma16816h(O[2 * nd + 1], a, vh[2], vh[3]);
            }
        }
        __syncthreads();
    }

    // ---- epilogue: fused fp16 hi/lo split write ----
    float inv0 = 1.f / l0, inv1 = 1.f / l1;
    #pragma unroll
    for (int nd = 0; nd < 8; nd++) {
        int d = h * HDIM + nd * 8 + c2;
        float o00 = O[nd][0] * inv0, o01 = O[nd][1] * inv0;
        float o10 = O[nd][2] * inv1, o11 = O[nd][3] * inv1;
        __half2 h0 = __floats2half2_rn(o00, o01);
        __half2 h1 = __floats2half2_rn(o10, o11);
        *(__half2*)&Yh[(size_t)row0 * DMODEL + d] = h0;
        *(__half2*)&Yh[(size_t)row1 * DMODEL + d] = h1;
        *(__half2*)&Yl[(size_t)row0 * DMODEL + d] =
            __floats2half2_rn(o00 - __low2float(h0), o01 - __high2float(h0));
        *(__half2*)&Yl[(size_t)row1 * DMODEL + d] =
            __floats2half2_rn(o10 - __low2float(h1), o11 - __high2float(h1));
    }
}

// ---------------- launch ----------------
extern "C" void kernel_launch(void* const* d_in, const int* in_sizes, int n_in,
                              void* d_out, int out_size) {
    const float* x      = (const float*)d_in[0];
    const float* w_qkv  = (const float*)d_in[1];
    const float* w_proj = (const float*)d_in[2];
    float* out = (float*)d_out;
    (void)in_sizes; (void)n_in; (void)out_size;

    float *p_v;
    __half *p_xh, *p_xl, *p_yh, *p_yl, *p_wq, *p_wp;
    __half *p_qfh, *p_qfl, *p_kf, *p_vfh;
    cudaGetSymbolAddress((void**)&p_v,  g_v);
    cudaGetSymbolAddress((void**)&p_xh, g_xh);
    cudaGetSymbolAddress((void**)&p_xl, g_xl);
    cudaGetSymbolAddress((void**)&p_yh, g_yh);
    cudaGetSymbolAddress((void**)&p_yl, g_yl);
    cudaGetSymbolAddress((void**)&p_wq, g_wq);
    cudaGetSymbolAddress((void**)&p_wp, g_wp);
    cudaGetSymbolAddress((void**)&p_qfh, g_qfh);
    cudaGetSymbolAddress((void**)&p_qfl, g_qfl);
    cudaGetSymbolAddress((void**)&p_kf,  g_kf);
    cudaGetSymbolAddress((void**)&p_vfh, g_vfh);

    cudaFuncSetAttribute(gemm_mma_kernel, cudaFuncAttributeMaxDynamicSharedMemorySize, GEMM_SMEM);
    cudaFuncSetAttribute(attn_mma_kernel, cudaFuncAttributeMaxDynamicSharedMemorySize, ATTN_SMEM);

    // 1. RoPE tables (needed by QKV epilogue)
    rope_table_kernel<<<(SEQ * HALF + 255) / 256, 256>>>();

    // 2. prep: x split (fp16), w_qkv transpose (fp16 single)
    split_half_kernel<<<(SEQ * DMODEL + 255) / 256, 256>>>(x, p_xh, p_xl, SEQ * DMODEL);
    {
        dim3 grid(3 * DMODEL / 32, DMODEL / 32);
        transpose_half_kernel<<<grid, dim3(32, 8)>>>(w_qkv, p_wq, DMODEL, 3 * DMODEL);
    }

    // 3. QKV projection with fused RoPE epilogue -> qfh/qfl, kf (fp16), v (fp32)
    {
        dim3 grid(3 * DMODEL / 128, SEQ / 128);
        gemm_mma_kernel<<<grid, 256, GEMM_SMEM>>>(p_xh, p_xl, p_wq,
                                                  nullptr, p_qfh, p_qfl, p_kf, p_v,
                                                  3 * DMODEL, DMODEL, 1);
    }

    // 4. V transpose (fp16 single)
    {
        dim3 grid(SEQ / 64, NHEAD);
        vsplit_kernel<<<grid, 256>>>();
    }

    // 5. flash attention on tensor cores; writes yh/yl fp16 split directly
    {
        dim3 grid(SEQ / 128, NHEAD);
        attn_mma_kernel<<<grid, 256, ATTN_SMEM>>>(p_qfh, p_qfl, p_kf, p_vfh, p_yh, p_yl);
    }

    // 6. output projection (w_proj transpose prepped here; independent of attention)
    {
        dim3 grid(DMODEL / 32, DMODEL / 32);
        transpose_half_kernel<<<grid, dim3(32, 8)>>>(w_proj, p_wp, DMODEL, DMODEL);
    }
    {
        dim3 grid(DMODEL / 128, SEQ / 128);
        gemm_mma_kernel<<<grid, 256, GEMM_SMEM>>>(p_yh, p_yl, p_wp,
                                                  out, nullptr, nullptr, nullptr, nullptr,
                                                  DMODEL, DMODEL, 0);
    }
}